// round 14
// baseline (speedup 1.0000x reference)
#include <cuda_runtime.h>
#include <cuda_fp16.h>
#include <math.h>
#include <stdint.h>

#define NT 16384
#define NE 16384
#define BETA 0.25f

#define RH  88                      // halves per padded row (80 data+extra, 8 pad)
#define RBH 176                     // bytes per row (11*16 -> conflict-free ldmatrix)
#define TILEH (128 * RBH)           // 22528
#define CHUNKH (TILEH / 16)         // 1408

#define CAP 128                     // candidate slots per token
#define MK1 4.0e-4f                 // q-domain margin slope * sqrt(zn)
#define MK2 7.0e-3f                 // q-domain margin offset (fp16-acc error + slack)

// ---------------- static device scratch ----------------
__device__ __half g_zh[16384 * RH];   // [zh | 1 | 0...] padded rows
__device__ __half g_eh[16384 * RH];   // [Eh | -2048*en | 0...] (E = 4096*e)
__device__ float g_enorm[NE];
__device__ float g_znorm[NT];
__device__ float g_thr[NT];           // acc-domain threshold: accmax - 2048*M
__device__ int   g_cand[NT * CAP];
__device__ int   g_ccnt[NT];
__device__ int   g_idx[NT];
__device__ int   g_counts[NE];
__device__ float g_loss;
__device__ float g_ent;
__device__ int   g_cu;
__device__ int   g_tick;

// ---------------- helpers ----------------
__device__ __forceinline__ uint32_t smem_u32(const void* p) {
    uint32_t a;
    asm("{ .reg .u64 t; cvta.to.shared.u64 t, %1; cvt.u32.u64 %0, t; }" : "=r"(a) : "l"(p));
    return a;
}
__device__ __forceinline__ __half2 u2h(uint32_t u) {
    return *reinterpret_cast<__half2*>(&u);
}

#define CP_ASYNC16(dst_u32, src_ptr) \
    asm volatile("cp.async.cg.shared.global [%0], [%1], 16;\n" :: "r"(dst_u32), "l"(src_ptr))
#define CP_COMMIT()  asm volatile("cp.async.commit_group;\n" ::: "memory")
#define CP_WAIT0()   asm volatile("cp.async.wait_group 0;\n" ::: "memory")

#define LDSM_X4(r, addr) \
    asm volatile("ldmatrix.sync.aligned.m8n8.x4.shared.b16 {%0,%1,%2,%3}, [%4];" \
        : "=r"((r)[0]), "=r"((r)[1]), "=r"((r)[2]), "=r"((r)[3]) : "r"(addr))
#define LDSM_X2(r, addr) \
    asm volatile("ldmatrix.sync.aligned.m8n8.x2.shared.b16 {%0,%1}, [%2];" \
        : "=r"((r)[0]), "=r"((r)[1]) : "r"(addr))

// fp16-accumulate mma (double-rate vs f32-acc)
__device__ __forceinline__ void mma16816h(uint32_t* c, const uint32_t* a, const uint32_t* b) {
    asm volatile(
        "mma.sync.aligned.m16n8k16.row.col.f16.f16.f16.f16 "
        "{%0,%1}, {%2,%3,%4,%5}, {%6,%7}, {%0,%1};"
        : "+r"(c[0]), "+r"(c[1])
        : "r"(a[0]), "r"(a[1]), "r"(a[2]), "r"(a[3]), "r"(b[0]), "r"(b[1]));
}

// ---------------- prep: h tiles with folded norm column; zero state ----------------
__global__ void k_split(const float* __restrict__ z, const float* __restrict__ emb) {
    extern __shared__ __half st[];          // 128*RH halves = 22528 B
    int blk = blockIdx.x;                   // 0..127 z tiles, 128..255 e subtiles
    int tid = threadIdx.x;                  // 256
    if (blk < 128) {
        int tile = blk;
        int b = tile >> 3, hw0 = (tile & 7) << 7;
        for (int idx = tid; idx < 8192; idx += 256) {
            int k = idx >> 7, tl = idx & 127;
            float v = z[((size_t)(b * 64 + k) << 10) + hw0 + tl];
            st[tl * RH + k] = __float2half_rn(v);
        }
        // pad cols 64..87 (col 64 overwritten below with 1.0)
        for (int idx = tid; idx < 128 * 24; idx += 256) {
            int tl = idx / 24, c = 64 + idx % 24;
            st[tl * RH + c] = __ushort_as_half(0);
        }
        __syncthreads();
        if (tid < 128) {
            float s = 0.f;
            for (int k = 0; k < 64; k++) {
                float v = z[((size_t)(b * 64 + k) << 10) + hw0 + tid];
                s += v * v;
            }
            g_znorm[(tile << 7) + tid] = s;
            st[tid * RH + 64] = __float2half_rn(1.0f);
        }
        __syncthreads();
        float4* dst = (float4*)(g_zh + (size_t)tile * 128 * RH);
        const float4* src = (const float4*)st;
        for (int i = tid; i < CHUNKH; i += 256) dst[i] = src[i];
        if (tile == 0 && tid == 0) { g_loss = 0.f; g_ent = 0.f; g_cu = 0; g_tick = 0; }
    } else {
        int sub = blk - 128;
        int n0 = sub << 7;
        for (int idx = tid; idx < 8192; idx += 256) {
            int nl = idx >> 6, k = idx & 63;
            float v = emb[(size_t)(n0 + nl) * 64 + k] * 4096.0f;   // exact scale
            st[nl * RH + k] = __float2half_rn(v);
        }
        for (int idx = tid; idx < 128 * 24; idx += 256) {
            int nl = idx / 24, c = 64 + idx % 24;
            st[nl * RH + c] = __ushort_as_half(0);
        }
        __syncthreads();
        if (tid < 128) {
            float s = 0.f;
            for (int k = 0; k < 64; k++) {
                float v = emb[(size_t)(n0 + tid) * 64 + k];
                s += v * v;
            }
            g_enorm[n0 + tid] = s;
            st[tid * RH + 64] = __float2half_rn(-2048.0f * s);
            g_counts[n0 + tid] = 0;
            g_ccnt[n0 + tid] = 0;
        }
        __syncthreads();
        float4* dst = (float4*)(g_eh + (size_t)sub * 128 * RH);
        const float4* src = (const float4*)st;
        for (int i = tid; i < CHUNKH; i += 256) dst[i] = src[i];
    }
}

// hh+norm mma over K=80 tiles; acc[mi][ni][rh] = half2 (2 cols); acc = -2^11 * q
__device__ __forceinline__ void mma_phase_h16(uint32_t a_base, uint32_t b_base,
                                              uint32_t acc[4][4][2]) {
#pragma unroll
    for (int mi = 0; mi < 4; mi++)
#pragma unroll
        for (int ni = 0; ni < 4; ni++) { acc[mi][ni][0] = 0u; acc[mi][ni][1] = 0u; }
#pragma unroll
    for (int ks = 0; ks < 5; ks++) {
        uint32_t ah[4][4], bh[4][2];
#pragma unroll
        for (int mi = 0; mi < 4; mi++)
            LDSM_X4(ah[mi], a_base + mi * 16 * RBH + ks * 32);
#pragma unroll
        for (int ni = 0; ni < 4; ni++)
            LDSM_X2(bh[ni], b_base + ni * 8 * RBH + ks * 32);
#pragma unroll
        for (int mi = 0; mi < 4; mi++)
#pragma unroll
            for (int ni = 0; ni < 4; ni++)
                mma16816h(acc[mi][ni], ah[mi], bh[ni]);
    }
}

// ---------------- pass A: value-only MAX of acc -> acc-domain threshold ------------
// smem: A [0,22528) | B ring x4  (total 112640)
#define SM_F (5 * TILEH)

__global__ void __launch_bounds__(256, 1) k_min() {
    extern __shared__ __align__(16) unsigned char sm[];
    uint32_t sb = smem_u32(sm);
    const uint32_t SA = sb, SBB = sb + TILEH;

    int tid = threadIdx.x, lane = tid & 31, wid = tid >> 5;
    int mw = wid & 1, nw = wid >> 1;        // 2 x 4 warp grid
    int mbase = mw * 64, nbw = nw * 32;     // warp tile 64 x 32

    {
        const char* gz = (const char*)(g_zh + (size_t)blockIdx.x * 128 * RH);
        for (int i = tid; i < CHUNKH; i += 256) CP_ASYNC16(SA + i * 16, gz + i * 16);
        const char* ge0 = (const char*)g_eh;
        for (int i = tid; i < CHUNKH; i += 256) CP_ASYNC16(SBB + i * 16, ge0 + i * 16);
        const char* ge1 = (const char*)(g_eh + (size_t)128 * RH);
        for (int i = tid; i < CHUNKH; i += 256) CP_ASYNC16(SBB + TILEH + i * 16, ge1 + i * 16);
        CP_COMMIT(); CP_WAIT0();
    }
    __syncthreads();

    float bmax[8];
#pragma unroll
    for (int r = 0; r < 8; r++) bmax[r] = -3.0e38f;

    uint32_t a_base = SA + (uint32_t)(mbase + (lane & 15)) * RBH + ((lane >> 4) & 1) * 16;
    uint32_t b_roff = (uint32_t)(nbw + (lane & 7)) * RBH + ((lane >> 3) & 1) * 16;

    uint32_t acc[4][4][2];

    for (int kp = 0; kp < 64; kp++) {
        int j0 = 2 * kp, j1 = j0 + 1;
        uint32_t s0 = SBB + (uint32_t)(j0 & 3) * TILEH;
        uint32_t s1 = SBB + (uint32_t)(j1 & 3) * TILEH;

        if (j0 + 2 < 128) {
            const char* p0 = (const char*)(g_eh + (size_t)(j0 + 2) * 128 * RH);
            uint32_t d0 = SBB + (uint32_t)((j0 + 2) & 3) * TILEH;
            for (int i = tid; i < CHUNKH; i += 256) CP_ASYNC16(d0 + i * 16, p0 + i * 16);
            const char* p1 = (const char*)(g_eh + (size_t)(j1 + 2) * 128 * RH);
            uint32_t d1 = SBB + (uint32_t)((j1 + 2) & 3) * TILEH;
            for (int i = tid; i < CHUNKH; i += 256) CP_ASYNC16(d1 + i * 16, p1 + i * 16);
            CP_COMMIT();
        }

#pragma unroll
        for (int half = 0; half < 2; half++) {
            uint32_t bb = (half ? s1 : s0) + b_roff;
            mma_phase_h16(a_base, bb, acc);
#pragma unroll
            for (int mi = 0; mi < 4; mi++) {
#pragma unroll
                for (int rh = 0; rh < 2; rh++) {
                    __half2 m = __hmax2(__hmax2(u2h(acc[mi][0][rh]), u2h(acc[mi][1][rh])),
                                        __hmax2(u2h(acc[mi][2][rh]), u2h(acc[mi][3][rh])));
                    float f = fmaxf(__low2float(m), __high2float(m));
                    bmax[mi * 2 + rh] = fmaxf(bmax[mi * 2 + rh], f);
                }
            }
        }

        CP_WAIT0();
        __syncthreads();
    }

    // quad reduce then cross-warp reduce -> per-token acc-domain threshold
#pragma unroll
    for (int r = 0; r < 8; r++) {
        bmax[r] = fmaxf(bmax[r], __shfl_xor_sync(0xffffffffu, bmax[r], 1));
        bmax[r] = fmaxf(bmax[r], __shfl_xor_sync(0xffffffffu, bmax[r], 2));
    }
    __syncthreads();
    float* rv = (float*)sm;                          // 128 rows x 4 nwarps
    if ((lane & 3) == 0) {
#pragma unroll
        for (int r = 0; r < 8; r++) {
            int row = mbase + (r >> 1) * 16 + (r & 1) * 8 + (lane >> 2);
            rv[row * 4 + nw] = bmax[r];
        }
    }
    __syncthreads();
    if (tid < 128) {
        float v = fmaxf(fmaxf(rv[tid * 4], rv[tid * 4 + 1]),
                        fmaxf(rv[tid * 4 + 2], rv[tid * 4 + 3]));
        int t = (blockIdx.x << 7) + tid;
        float zn = g_znorm[t];
        // acc >= athr  <=>  q <= qmin + M
        g_thr[t] = v - fmaf(sqrtf(zn), 2048.0f * MK1, 2048.0f * MK2);
    }
}

// ---------------- pass B: identical GEMM, collect candidates (acc >= athr) ---------
__global__ void __launch_bounds__(256, 1) k_coll() {
    extern __shared__ __align__(16) unsigned char sm[];
    uint32_t sb = smem_u32(sm);
    const uint32_t SA = sb, SBB = sb + TILEH;

    int tid = threadIdx.x, lane = tid & 31, wid = tid >> 5;
    int mw = wid & 1, nw = wid >> 1;
    int mbase = mw * 64, nbw = nw * 32;

    {
        const char* gz = (const char*)(g_zh + (size_t)blockIdx.x * 128 * RH);
        for (int i = tid; i < CHUNKH; i += 256) CP_ASYNC16(SA + i * 16, gz + i * 16);
        const char* ge0 = (const char*)g_eh;
        for (int i = tid; i < CHUNKH; i += 256) CP_ASYNC16(SBB + i * 16, ge0 + i * 16);
        const char* ge1 = (const char*)(g_eh + (size_t)128 * RH);
        for (int i = tid; i < CHUNKH; i += 256) CP_ASYNC16(SBB + TILEH + i * 16, ge1 + i * 16);
        CP_COMMIT(); CP_WAIT0();
    }
    __syncthreads();

    float thr[8]; int tok[8];
#pragma unroll
    for (int mi = 0; mi < 4; mi++)
#pragma unroll
        for (int rh = 0; rh < 2; rh++) {
            int t = (blockIdx.x << 7) + mbase + mi * 16 + rh * 8 + (lane >> 2);
            tok[mi * 2 + rh] = t;
            thr[mi * 2 + rh] = g_thr[t];
        }

    uint32_t a_base = SA + (uint32_t)(mbase + (lane & 15)) * RBH + ((lane >> 4) & 1) * 16;
    uint32_t b_roff = (uint32_t)(nbw + (lane & 7)) * RBH + ((lane >> 3) & 1) * 16;

    uint32_t acc[4][4][2];

    for (int kp = 0; kp < 64; kp++) {
        int j0 = 2 * kp, j1 = j0 + 1;
        uint32_t s0 = SBB + (uint32_t)(j0 & 3) * TILEH;
        uint32_t s1 = SBB + (uint32_t)(j1 & 3) * TILEH;

        if (j0 + 2 < 128) {
            const char* p0 = (const char*)(g_eh + (size_t)(j0 + 2) * 128 * RH);
            uint32_t d0 = SBB + (uint32_t)((j0 + 2) & 3) * TILEH;
            for (int i = tid; i < CHUNKH; i += 256) CP_ASYNC16(d0 + i * 16, p0 + i * 16);
            const char* p1 = (const char*)(g_eh + (size_t)(j1 + 2) * 128 * RH);
            uint32_t d1 = SBB + (uint32_t)((j1 + 2) & 3) * TILEH;
            for (int i = tid; i < CHUNKH; i += 256) CP_ASYNC16(d1 + i * 16, p1 + i * 16);
            CP_COMMIT();
        }

#pragma unroll
        for (int half = 0; half < 2; half++) {
            int j = half ? j1 : j0;
            uint32_t bb = (half ? s1 : s0) + b_roff;
            mma_phase_h16(a_base, bb, acc);
            int jbase = j << 7;
#pragma unroll
            for (int mi = 0; mi < 4; mi++) {
#pragma unroll
                for (int rh = 0; rh < 2; rh++) {
                    int r = mi * 2 + rh;
                    __half2 m = __hmax2(__hmax2(u2h(acc[mi][0][rh]), u2h(acc[mi][1][rh])),
                                        __hmax2(u2h(acc[mi][2][rh]), u2h(acc[mi][3][rh])));
                    float f = fmaxf(__low2float(m), __high2float(m));
                    if (f >= thr[r]) {      // rare: threshold = final max - margin
                        int t = tok[r];
#pragma unroll
                        for (int ni = 0; ni < 4; ni++) {
                            float2 fq = __half22float2(u2h(acc[mi][ni][rh]));
                            if (fq.x >= thr[r]) {
                                int n = jbase + nbw + ni * 8 + (lane & 3) * 2;
                                int slot = atomicAdd(&g_ccnt[t], 1);
                                if (slot < CAP) g_cand[t * CAP + slot] = n;
                            }
                            if (fq.y >= thr[r]) {
                                int n = jbase + nbw + ni * 8 + (lane & 3) * 2 + 1;
                                int slot = atomicAdd(&g_ccnt[t], 1);
                                if (slot < CAP) g_cand[t * CAP + slot] = n;
                            }
                        }
                    }
                }
            }
        }

        CP_WAIT0();
        __syncthreads();
    }
}

// ---------------- pass C: exact fp32 refine over candidates (R1 formula) -----------
__global__ void k_refine(const float* __restrict__ z, const float* __restrict__ emb,
                         float* __restrict__ out) {
    __shared__ float zs[8][64];
    int w = threadIdx.x >> 5, lane = threadIdx.x & 31;
    int t = blockIdx.x * 8 + w;
    int b = t >> 10, hw = t & 1023;
    zs[w][lane]      = z[((size_t)(b * 64 + lane) << 10) + hw];
    zs[w][lane + 32] = z[((size_t)(b * 64 + lane + 32) << 10) + hw];
    __syncwarp();
    float zn = g_znorm[t];
    int c = g_ccnt[t];
    float bd = 3.0e38f; int bn = 0x7fffffff;
    if (c <= CAP) {
        for (int i = lane; i < c; i += 32) {
            int n = g_cand[t * CAP + i];
            const float* er = emb + (size_t)n * 64;
            float acc = 0.f;
#pragma unroll
            for (int k = 0; k < 64; k++) acc = fmaf(zs[w][k], er[k], acc);
            float d = __fsub_rn(__fadd_rn(zn, g_enorm[n]), __fmul_rn(2.0f, acc));
            if (d < bd || (d == bd && n < bn)) { bd = d; bn = n; }
        }
    } else {
        // overflow fallback: exact scan of all codes (correctness net)
        for (int n = lane; n < NE; n += 32) {
            const float* er = emb + (size_t)n * 64;
            float acc = 0.f;
#pragma unroll
            for (int k = 0; k < 64; k++) acc = fmaf(zs[w][k], er[k], acc);
            float d = __fsub_rn(__fadd_rn(zn, g_enorm[n]), __fmul_rn(2.0f, acc));
            if (d < bd || (d == bd && n < bn)) { bd = d; bn = n; }
        }
    }
#pragma unroll
    for (int off = 16; off > 0; off >>= 1) {
        float od = __shfl_xor_sync(0xffffffffu, bd, off);
        int   on = __shfl_xor_sync(0xffffffffu, bn, off);
        if (od < bd || (od == bd && on < bn)) { bd = od; bn = on; }
    }
    if (lane == 0) {
        g_idx[t] = bn;
        out[1048579 + t] = (float)bn;
        atomicAdd(&g_counts[bn], 1);
    }
}

// ---------------- z_q gather + loss accumulation ----------------
__global__ void k_zq(const float* __restrict__ z, const float* __restrict__ emb,
                     float* __restrict__ out) {
    int p = blockIdx.x;            // 1024 planes = (b,c)
    int b = p >> 6, c = p & 63;
    int tid = threadIdx.x;         // 256
    float ls = 0.f;
    for (int hw = tid; hw < 1024; hw += 256) {
        int t = (b << 10) + hw;
        int id = g_idx[t];
        float v  = emb[(size_t)id * 64 + c];
        float zv = z[(size_t)p * 1024 + hw];
        out[(size_t)p * 1024 + hw] = v;
        float df = v - zv;
        ls += df * df;
    }
    __shared__ float red[8];
    for (int o = 16; o > 0; o >>= 1) ls += __shfl_down_sync(0xffffffff, ls, o);
    if ((tid & 31) == 0) red[tid >> 5] = ls;
    __syncthreads();
    if (tid == 0) {
        float s = 0.f;
        for (int w = 0; w < 8; w++) s += red[w];
        atomicAdd(&g_loss, s);
    }
}

// ---------------- entropy (parallel) + final scalar writes (ticket) ----------------
__global__ void k_ent(float* __restrict__ out) {
    int tid = threadIdx.x;                      // 1024, grid 16
    int n = blockIdx.x * 1024 + tid;
    int c = g_counts[n];
    float avg = (float)c * (1.0f / 16384.0f);
    float term = avg * logf(avg + 1e-10f);
    int cu = (c > 0) ? 1 : 0;
    for (int o = 16; o > 0; o >>= 1) {
        term += __shfl_down_sync(0xffffffffu, term, o);
        cu   += __shfl_down_sync(0xffffffffu, cu, o);
    }
    __shared__ float se[32]; __shared__ int sc[32];
    if ((tid & 31) == 0) { se[tid >> 5] = term; sc[tid >> 5] = cu; }
    __syncthreads();
    if (tid == 0) {
        float s = 0.f; int k = 0;
        for (int w = 0; w < 32; w++) { s += se[w]; k += sc[w]; }
        atomicAdd(&g_ent, s);
        atomicAdd(&g_cu, k);
        __threadfence();
        int tk = atomicAdd(&g_tick, 1);
        if (tk == 15) {
            out[1048576] = g_loss * (1.0f + BETA) / 1048576.0f;
            out[1048577] = expf(-g_ent);
            out[1048578] = (float)g_cu;
        }
    }
}

// ---------------- launch ----------------
extern "C" void kernel_launch(void* const* d_in, const int* in_sizes, int n_in,
                              void* d_out, int out_size) {
    const float* z   = (const float*)d_in[0];   // (16,64,32,32)
    const float* emb = (const float*)d_in[1];   // (16384,64)
    float* out = (float*)d_out;

    cudaFuncSetAttribute(k_split, cudaFuncAttributeMaxDynamicSharedMemorySize, TILEH);
    cudaFuncSetAttribute(k_min,   cudaFuncAttributeMaxDynamicSharedMemorySize, SM_F);
    cudaFuncSetAttribute(k_coll,  cudaFuncAttributeMaxDynamicSharedMemorySize, SM_F);

    k_split<<<256, 256, TILEH>>>(z, emb);
    k_min<<<128, 256, SM_F>>>();
    k_coll<<<128, 256, SM_F>>>();
    k_refine<<<2048, 256>>>(z, emb, out);
    k_zq<<<1024, 256>>>(z, emb, out);
    k_ent<<<16, 1024>>>(out);
}